// round 16
// baseline (speedup 1.0000x reference)
#include <cuda_runtime.h>
#include <cstdint>

#define NMAX 100000
#define EMAX 3300000
#define MMAX 8192
#define KINF 0xFFFFFFFFFFFFFFFFULL
#define MAXB 1024

// ---------------- static device scratch (no allocations allowed) -------------
__device__ unsigned long long g_key[NMAX];
__device__ unsigned long long g_minCur[NMAX];
__device__ unsigned long long g_minNew[NMAX];
__device__ unsigned char g_mask[NMAX];
__device__ unsigned char g_maskP[NMAX];
__device__ unsigned char g_mis[NMAX];
__device__ int g_misIdx[NMAX];
__device__ int g_cluster[NMAX];
__device__ unsigned int g_dense[(size_t)MMAX * (size_t)MMAX];  // u32 fixed-point, 0 = absent
__device__ unsigned long long g_pair[EMAX];   // (cr<<13|cc)<<32 | inc  (edge order)
__device__ unsigned long long g_trip[EMAX];   // same, row-bucketed
__device__ int g_rowCnt[MMAX + 8];
__device__ int g_rowOff[MMAX + 8];
__device__ int g_rowCur[MMAX + 8];
__device__ int g_nodeCnt[MAXB];
__device__ int g_nodeOff[MAXB];
__device__ int g_cellCnt[MAXB];
__device__ int g_cellOff[MAXB];
__device__ int g_cnt2[2];
__device__ unsigned long long g_maxMisKey;
__device__ int g_M;
__device__ int g_P;
__device__ unsigned int g_arrive;

// ---------------- helpers ----------------------------------------------------

__device__ __forceinline__ void grid_bar(unsigned nb, unsigned &target) {
    __threadfence();
    __syncthreads();
    if (threadIdx.x == 0) {
        target += nb;
        atomicAdd(&g_arrive, 1u);
        while (*((volatile unsigned*)&g_arrive) < target) __nanosleep(64);
        __threadfence();
    }
    __syncthreads();
}

__device__ __forceinline__ int block_reduce_add(int v) {
    __shared__ int shr[32];
    int lane = threadIdx.x & 31;
    int w = threadIdx.x >> 5;
    #pragma unroll
    for (int o = 16; o; o >>= 1) v += __shfl_down_sync(0xffffffffu, v, o);
    if (lane == 0) shr[w] = v;
    __syncthreads();
    int nw = (blockDim.x + 31) >> 5;
    int r = 0;
    if (w == 0) {
        r = (lane < nw) ? shr[lane] : 0;
        #pragma unroll
        for (int o = 16; o; o >>= 1) r += __shfl_down_sync(0xffffffffu, r, o);
    }
    __syncthreads();
    return r;  // valid on threadIdx.x == 0
}

__device__ __forceinline__ int block_excl_scan(int v, int &total) {
    __shared__ int sh[1024];
    int t = threadIdx.x;
    sh[t] = v;
    __syncthreads();
    for (int off = 1; off < blockDim.x; off <<= 1) {
        int y = (t >= off) ? sh[t - off] : 0;
        __syncthreads();
        sh[t] += y;
        __syncthreads();
    }
    int incl = sh[t];
    total = sh[blockDim.x - 1];
    __syncthreads();
    return incl - v;
}

// read-filtered atomicMin: stale read >= actual, so skipping when mv >= cur is safe.
__device__ __forceinline__ void propF(int row, int col) {
    unsigned long long mv = g_minCur[row];
    if (mv != KINF) {
        unsigned long long c = g_minNew[col];
        if (mv < c) atomicMin(&g_minNew[col], mv);
    }
}
__device__ __forceinline__ void dil(int row, int col) {
    if (g_mask[row]) g_maskP[col] = 1;
}

// ---------------- kernels -----------------------------------------------------

__global__ void k_init(const float* __restrict__ score, int n) {
    int v = blockIdx.x * blockDim.x + threadIdx.x;
    if (v < n) {
        unsigned long long k =
            ((unsigned long long)__float_as_uint(score[v]) << 32) | (unsigned)v;
        g_key[v] = k; g_minCur[v] = k; g_minNew[v] = k;
        g_mask[v] = 0; g_maskP[v] = 0; g_mis[v] = 0;
    }
    if (v < MMAX + 8) g_rowCnt[v] = 0;
    if (v == 0) {
        g_arrive = 0;
        g_cnt2[0] = 0; g_cnt2[1] = 1;   // slot 1 read at top of round 0
        g_maxMisKey = 0; g_M = 0; g_P = 0;
    }
}

// Persistent kernel: full MIS loop + clustering (R1-proven, frozen).
__global__ void __launch_bounds__(256, 4)
k_persist(const int* __restrict__ erow, const int* __restrict__ ecol,
          int n, int e, const float* __restrict__ x, int d,
          float* __restrict__ out)
{
    const unsigned nb = gridDim.x;
    const unsigned nt = nb * blockDim.x;
    const unsigned tid = blockIdx.x * blockDim.x + threadIdx.x;
    unsigned bt = 0;
    const bool vecok = ((e & 3) == 0);
    const unsigned e4 = (unsigned)e >> 2;

    for (int round = 0; round < 100000; ++round) {
        if (*((volatile int*)&g_cnt2[(round + 1) & 1]) == 0) break;

        // A: min-key propagation
        if (vecok) {
            for (unsigned i = tid; i < e4; i += nt) {
                int4 r = __ldg((const int4*)erow + i);
                int4 c = __ldg((const int4*)ecol + i);
                propF(r.x, c.x); propF(r.y, c.y);
                propF(r.z, c.z); propF(r.w, c.w);
            }
        } else {
            for (unsigned i = tid; i < (unsigned)e; i += nt)
                propF(erow[i], ecol[i]);
        }
        grid_bar(nb, bt);

        // B: local minima join MIS
        if (tid == 0) g_cnt2[(round + 1) & 1] = 0;
        for (unsigned v = tid; v < (unsigned)n; v += nt) {
            unsigned char m = g_mask[v];
            if (!m && g_key[v] == g_minNew[v]) { g_mis[v] = 1; g_mask[v] = 1; m = 1; }
            g_maskP[v] = m;
        }
        grid_bar(nb, bt);

        // C: mask dilation by exactly 1 hop
        if (vecok) {
            for (unsigned i = tid; i < e4; i += nt) {
                int4 r = __ldg((const int4*)erow + i);
                int4 c = __ldg((const int4*)ecol + i);
                dil(r.x, c.x); dil(r.y, c.y); dil(r.z, c.z); dil(r.w, c.w);
            }
        } else {
            for (unsigned i = tid; i < (unsigned)e; i += nt)
                dil(erow[i], ecol[i]);
        }
        grid_bar(nb, bt);

        // D: commit mask, reset min arrays, count unmasked
        int local = 0;
        for (unsigned v = tid; v < (unsigned)n; v += nt) {
            unsigned char m = g_maskP[v];
            g_mask[v] = m;
            unsigned long long val = m ? KINF : g_key[v];
            g_minCur[v] = val; g_minNew[v] = val;
            local += (m == 0);
        }
        int bs = block_reduce_add(local);
        if (threadIdx.x == 0 && bs) atomicAdd(&g_cnt2[round & 1], bs);
        grid_bar(nb, bt);
    }

    // ---------------- clustering ---------------------------------------------
    for (unsigned v = tid; v < (unsigned)n; v += nt) {
        unsigned long long mc;
        if (g_mis[v]) { mc = g_key[v]; atomicMax(&g_maxMisKey, mc); }
        else mc = KINF;
        g_minCur[v] = mc; g_minNew[v] = mc;
    }
    int chunk = (n + (int)nb - 1) / (int)nb;
    int cs = (int)blockIdx.x * chunk;
    int ce = cs + chunk; if (ce > n) ce = n;
    {
        int cnt = 0;
        for (int v = cs + (int)threadIdx.x; v < ce; v += (int)blockDim.x)
            cnt += g_mis[v];
        int bs = block_reduce_add(cnt);
        if (threadIdx.x == 0) g_nodeCnt[blockIdx.x] = bs;
    }
    grid_bar(nb, bt);

    if (blockIdx.x == 0 && threadIdx.x == 0) {
        int s = 0;
        for (unsigned i = 0; i < nb; ++i) { int c = g_nodeCnt[i]; g_nodeOff[i] = s; s += c; }
        if (s > MMAX) s = MMAX;
        g_M = s;
    }
    grid_bar(nb, bt);

    {
        int run = g_nodeOff[blockIdx.x];
        for (int t0 = cs; t0 < ce; t0 += (int)blockDim.x) {
            int v = t0 + (int)threadIdx.x;
            int f = (v < ce) ? (int)g_mis[v] : 0;
            int tot;
            int ex = block_excl_scan(f, tot);
            if (v < ce) g_misIdx[v] = run + ex;
            run += tot;
        }
    }
    grid_bar(nb, bt);

    // H: one min-key propagation (k = 1), full edge list
    if (vecok) {
        for (unsigned i = tid; i < e4; i += nt) {
            int4 r = __ldg((const int4*)erow + i);
            int4 c = __ldg((const int4*)ecol + i);
            propF(r.x, c.x); propF(r.y, c.y); propF(r.z, c.z); propF(r.w, c.w);
        }
    } else {
        for (unsigned i = tid; i < (unsigned)e; i += nt)
            propF(erow[i], ecol[i]);
    }
    grid_bar(nb, bt);

    // I: cluster assignment
    int fb = g_misIdx[(unsigned)(g_maxMisKey & 0xffffffffULL)];
    for (unsigned v = tid; v < (unsigned)n; v += nt) {
        unsigned long long mk = g_minNew[v];
        g_cluster[v] = (mk == KINF) ? fb : g_misIdx[(unsigned)(mk & 0xffffffffULL)];
    }

    // J: x_out = x[mis]
    if ((d & 3) == 0) {
        int dv = d >> 2;
        for (unsigned v = tid; v < (unsigned)n; v += nt) {
            if (g_mis[v]) {
                const float4* src = (const float4*)(x + (size_t)v * d);
                float4* dst = (float4*)(out + (size_t)g_misIdx[v] * d);
                for (int j = 0; j < dv; ++j) dst[j] = src[j];
            }
        }
    } else {
        for (unsigned v = tid; v < (unsigned)n; v += nt) {
            if (g_mis[v]) {
                const float* src = x + (size_t)v * d;
                float* dst = out + (size_t)g_misIdx[v] * d;
                for (int j = 0; j < d; ++j) dst[j] = src[j];
            }
        }
    }
}

// ---------------- dense pipeline (u32 fixed-point) -----------------------------
// inc = round(attr*2^16) + 1 guarantees presence; integer adds commute exactly.
// R16: edges are row-bucketed before accumulation so REDs into g_dense have
// DRAM-page locality (contiguous per-block chunks span ~6 dense rows).

__global__ void k_zero() {
    size_t MM = (size_t)g_M * (size_t)g_M;
    size_t nt = (size_t)gridDim.x * blockDim.x;
    for (size_t i = (size_t)blockIdx.x * blockDim.x + threadIdx.x; i < MM; i += nt)
        g_dense[i] = 0u;
}

// pack: (cr<<13|cc)<<32 | inc, plus histogram of cluster rows.
__global__ void k_pack(const int* __restrict__ erow, const int* __restrict__ ecol,
                       const float* __restrict__ attr, int e) {
    unsigned nt = gridDim.x * blockDim.x;
    unsigned t = blockIdx.x * blockDim.x + threadIdx.x;
    const float SC = 65536.0f;
    if ((e & 3) == 0) {
        unsigned e4 = (unsigned)e >> 2;
        for (unsigned i = t; i < e4; i += nt) {
            int4 r = __ldg((const int4*)erow + i);
            int4 c = __ldg((const int4*)ecol + i);
            float4 a = __ldg((const float4*)attr + i);
            unsigned cr0 = (unsigned)g_cluster[r.x], cc0 = (unsigned)g_cluster[c.x];
            unsigned cr1 = (unsigned)g_cluster[r.y], cc1 = (unsigned)g_cluster[c.y];
            unsigned cr2 = (unsigned)g_cluster[r.z], cc2 = (unsigned)g_cluster[c.z];
            unsigned cr3 = (unsigned)g_cluster[r.w], cc3 = (unsigned)g_cluster[c.w];
            g_pair[4*i+0] = ((unsigned long long)((cr0 << 13) | cc0) << 32) | (__float2uint_rn(a.x * SC) + 1u);
            g_pair[4*i+1] = ((unsigned long long)((cr1 << 13) | cc1) << 32) | (__float2uint_rn(a.y * SC) + 1u);
            g_pair[4*i+2] = ((unsigned long long)((cr2 << 13) | cc2) << 32) | (__float2uint_rn(a.z * SC) + 1u);
            g_pair[4*i+3] = ((unsigned long long)((cr3 << 13) | cc3) << 32) | (__float2uint_rn(a.w * SC) + 1u);
            atomicAdd(&g_rowCnt[cr0], 1); atomicAdd(&g_rowCnt[cr1], 1);
            atomicAdd(&g_rowCnt[cr2], 1); atomicAdd(&g_rowCnt[cr3], 1);
        }
    } else {
        for (unsigned i = t; i < (unsigned)e; i += nt) {
            unsigned cr = (unsigned)g_cluster[erow[i]];
            unsigned cc = (unsigned)g_cluster[ecol[i]];
            g_pair[i] = ((unsigned long long)((cr << 13) | cc) << 32)
                        | (__float2uint_rn(attr[i] * SC) + 1u);
            atomicAdd(&g_rowCnt[cr], 1);
        }
    }
}

// exclusive scan of rowCnt[0..8192) -> rowCur. 1 block of 1024, 8 per thread.
__global__ void k_scanB() {
    int t = threadIdx.x;
    int base = t * 8;
    int loc[8]; int s = 0;
    #pragma unroll
    for (int j = 0; j < 8; ++j) { loc[j] = s; s += g_rowCnt[base + j]; }
    int tot;
    int ex = block_excl_scan(s, tot);
    #pragma unroll
    for (int j = 0; j < 8; ++j) g_rowCur[base + j] = ex + loc[j];
    if (t == 0) g_rowOff[MMAX] = tot;
}

// scatter packed entries into row buckets (g_trip).
__global__ void k_scatter(int e) {
    unsigned nt = gridDim.x * blockDim.x;
    for (unsigned i = blockIdx.x * blockDim.x + threadIdx.x; i < (unsigned)e; i += nt) {
        unsigned long long p = g_pair[i];
        unsigned cr = (unsigned)(p >> 45);
        int pos = atomicAdd(&g_rowCur[cr], 1);
        g_trip[pos] = p;
    }
}

// accumulate bucketed entries into dense; contiguous per-block chunks give each
// block a ~6-row (160 KB) target window -> DRAM-page-local REDs. Return unused.
__global__ void k_accumB(int e) {
    unsigned M = (unsigned)g_M;
    unsigned chunk = ((unsigned)e + gridDim.x - 1) / gridDim.x;
    unsigned s = blockIdx.x * chunk;
    unsigned epos = s + chunk; if (epos > (unsigned)e) epos = (unsigned)e;
    for (unsigned i = s + threadIdx.x; i < epos; i += blockDim.x) {
        unsigned long long p = g_trip[i];
        unsigned k = (unsigned)(p >> 32);
        atomicAdd(&g_dense[(size_t)(k >> 13) * M + (k & 8191u)], (unsigned)p);
    }
}

// k_count: uint4-vectorized presence count (chunk = multiple of 4, matches k_write).
__global__ void k_count() {
    unsigned M = (unsigned)g_M;
    size_t MM = (size_t)M * M;
    size_t chunk = (((MM + gridDim.x - 1) / gridDim.x) + 3) & ~(size_t)3;
    size_t s = (size_t)blockIdx.x * chunk;
    int cnt = 0;
    if (s < MM) {
        size_t epos = s + chunk; if (epos > MM) epos = MM;
        size_t n4 = (epos - s) >> 2;
        const uint4* p4 = (const uint4*)(g_dense + s);
        for (size_t j = threadIdx.x; j < n4; j += blockDim.x) {
            uint4 v = p4[j];
            unsigned i0 = (unsigned)(s + (j << 2));
            if (v.x) { unsigned r = i0 / M;       cnt += (i0       - r * M) != r; }
            if (v.y) { unsigned r = (i0+1) / M;   cnt += ((i0+1)   - r * M) != r; }
            if (v.z) { unsigned r = (i0+2) / M;   cnt += ((i0+2)   - r * M) != r; }
            if (v.w) { unsigned r = (i0+3) / M;   cnt += ((i0+3)   - r * M) != r; }
        }
        for (size_t i = s + (n4 << 2) + threadIdx.x; i < epos; i += blockDim.x) {
            if (g_dense[i]) {
                unsigned ii = (unsigned)i;
                unsigned r = ii / M;
                cnt += ((ii - r * M) != r);
            }
        }
    }
    int bs = block_reduce_add(cnt);
    if (threadIdx.x == 0) g_cellCnt[blockIdx.x] = bs;
}

__global__ void k_scan(int nb2) {
    int t = threadIdx.x;
    int v = (t < nb2) ? g_cellCnt[t] : 0;
    int tot;
    int ex = block_excl_scan(v, tot);
    if (t < nb2) g_cellOff[t] = ex;
    if (t == 0) g_P = tot;
}

// k_write: ballot-based tile compaction (order preserved).
__global__ void k_write(float* __restrict__ out, int d) {
    __shared__ int wtot[8];
    unsigned M = (unsigned)g_M;
    size_t MM = (size_t)M * M;
    size_t P = (size_t)g_P;
    size_t xoff = (size_t)M * (size_t)d;
    size_t chunk = (((MM + gridDim.x - 1) / gridDim.x) + 3) & ~(size_t)3;
    size_t s = (size_t)blockIdx.x * chunk;
    if (s >= MM) return;
    size_t epos = s + chunk; if (epos > MM) epos = MM;
    size_t base = (size_t)g_cellOff[blockIdx.x];
    const float INV = 1.0f / 65536.0f;
    int lane = threadIdx.x & 31;
    int wid = threadIdx.x >> 5;
    unsigned lmask = (1u << lane) - 1u;

    for (size_t t0 = s; t0 < epos; t0 += blockDim.x) {
        size_t i = t0 + threadIdx.x;
        int keep = 0; unsigned r = 0, c = 0; float val = 0.f;
        if (i < epos) {
            unsigned a = g_dense[i];
            if (a != 0u) {
                unsigned ii = (unsigned)i;
                r = ii / M; c = ii - r * M;
                if (r != c) { keep = 1; val = (float)a * INV; }
            }
        }
        unsigned bal = __ballot_sync(0xffffffffu, keep);
        if (lane == 0) wtot[wid] = __popc(bal);
        __syncthreads();
        int pre = 0, tileTot = 0;
        #pragma unroll
        for (int w2 = 0; w2 < 8; ++w2) {
            int v2 = wtot[w2];
            pre += (w2 < wid) ? v2 : 0;
            tileTot += v2;
        }
        if (keep) {
            size_t p = base + (size_t)(pre + __popc(bal & lmask));
            out[xoff + p] = (float)r;
            out[xoff + P + p] = (float)c;
            out[xoff + 2 * P + p] = val;
        }
        base += (size_t)tileTot;
        __syncthreads();
    }
}

__global__ void k_tail(float* __restrict__ out, const float* __restrict__ score,
                       int n, int d) {
    int v = blockIdx.x * blockDim.x + threadIdx.x;
    if (v >= n) return;
    size_t off = (size_t)g_M * (size_t)d + 3 * (size_t)g_P;
    out[off + v] = (float)g_cluster[v];
    out[off + (size_t)n + v] = g_mis[v] ? 1.0f : 0.0f;
    out[off + 2 * (size_t)n + v] = score[v];
}

// ---------------- entry -------------------------------------------------------
extern "C" void kernel_launch(void* const* d_in, const int* in_sizes, int n_in,
                              void* d_out, int out_size) {
    const float* x = (const float*)d_in[0];
    const int* ei = (const int*)d_in[1];
    const float* attr = (const float*)d_in[2];
    const float* score = (const float*)d_in[3];
    int n = in_sizes[3];
    int e = in_sizes[1] / 2;
    int d = in_sizes[0] / n;
    const int* erow = ei;
    const int* ecol = ei + e;
    float* out = (float*)d_out;

    int dev = 0;
    cudaGetDevice(&dev);
    int sms = 148;
    cudaDeviceGetAttribute(&sms, cudaDevAttrMultiProcessorCount, dev);
    int nb = sms * 4;
    if (nb > MAXB) nb = MAXB;

    k_init<<<(n + 255) / 256, 256>>>(score, n);
    k_persist<<<nb, 256>>>(erow, ecol, n, e, x, d, out);
    k_zero<<<2048, 256>>>();
    k_pack<<<2048, 256>>>(erow, ecol, attr, e);
    k_scanB<<<1, 1024>>>();
    k_scatter<<<2048, 256>>>(e);
    k_accumB<<<MAXB, 256>>>(e);
    k_count<<<MAXB, 256>>>();
    k_scan<<<1, 1024>>>(MAXB);
    k_write<<<MAXB, 256>>>(out, d);
    k_tail<<<(n + 255) / 256, 256>>>(out, score, n, d);
}

// round 17
// speedup vs baseline: 1.8003x; 1.8003x over previous
#include <cuda_runtime.h>
#include <cstdint>

#define NMAX 100000
#define EMAX 3300000
#define MMAX 8192
#define KINF 0xFFFFFFFFFFFFFFFFULL
#define MAXB 1024

// ---------------- static device scratch (no allocations allowed) -------------
__device__ unsigned long long g_key[NMAX];
__device__ unsigned long long g_minCur[NMAX];
__device__ unsigned long long g_minNew[NMAX];
__device__ unsigned char g_mask[NMAX];
__device__ unsigned char g_maskP[NMAX];
__device__ unsigned char g_mis[NMAX];
__device__ int g_misIdx[NMAX];
__device__ int g_cluster[NMAX];
__device__ unsigned int g_dense[(size_t)MMAX * (size_t)MMAX];  // u32 fixed-point, 0 = absent
__device__ int g_nodeCnt[MAXB];
__device__ int g_nodeOff[MAXB];
__device__ int g_cellCnt[MAXB];
__device__ int g_cellOff[MAXB];
__device__ int g_cnt2[2];
__device__ unsigned long long g_maxMisKey;
__device__ int g_M;
__device__ int g_P;
__device__ unsigned int g_arrive;

// ---------------- helpers ----------------------------------------------------

__device__ __forceinline__ void grid_bar(unsigned nb, unsigned &target) {
    __threadfence();
    __syncthreads();
    if (threadIdx.x == 0) {
        target += nb;
        atomicAdd(&g_arrive, 1u);
        while (*((volatile unsigned*)&g_arrive) < target) __nanosleep(64);
        __threadfence();
    }
    __syncthreads();
}

__device__ __forceinline__ int block_reduce_add(int v) {
    __shared__ int shr[32];
    int lane = threadIdx.x & 31;
    int w = threadIdx.x >> 5;
    #pragma unroll
    for (int o = 16; o; o >>= 1) v += __shfl_down_sync(0xffffffffu, v, o);
    if (lane == 0) shr[w] = v;
    __syncthreads();
    int nw = (blockDim.x + 31) >> 5;
    int r = 0;
    if (w == 0) {
        r = (lane < nw) ? shr[lane] : 0;
        #pragma unroll
        for (int o = 16; o; o >>= 1) r += __shfl_down_sync(0xffffffffu, r, o);
    }
    __syncthreads();
    return r;  // valid on threadIdx.x == 0
}

__device__ __forceinline__ int block_excl_scan(int v, int &total) {
    __shared__ int sh[1024];
    int t = threadIdx.x;
    sh[t] = v;
    __syncthreads();
    for (int off = 1; off < blockDim.x; off <<= 1) {
        int y = (t >= off) ? sh[t - off] : 0;
        __syncthreads();
        sh[t] += y;
        __syncthreads();
    }
    int incl = sh[t];
    total = sh[blockDim.x - 1];
    __syncthreads();
    return incl - v;
}

// read-filtered atomicMin: stale read >= actual, so skipping when mv >= cur is safe.
__device__ __forceinline__ void propF(int row, int col) {
    unsigned long long mv = g_minCur[row];
    if (mv != KINF) {
        unsigned long long c = g_minNew[col];
        if (mv < c) atomicMin(&g_minNew[col], mv);
    }
}
__device__ __forceinline__ void dil(int row, int col) {
    if (g_mask[row]) g_maskP[col] = 1;
}

// ---------------- kernels -----------------------------------------------------

__global__ void k_init(const float* __restrict__ score, int n) {
    int v = blockIdx.x * blockDim.x + threadIdx.x;
    if (v < n) {
        unsigned long long k =
            ((unsigned long long)__float_as_uint(score[v]) << 32) | (unsigned)v;
        g_key[v] = k; g_minCur[v] = k; g_minNew[v] = k;
        g_mask[v] = 0; g_maskP[v] = 0; g_mis[v] = 0;
    }
    if (v == 0) {
        g_arrive = 0;
        g_cnt2[0] = 0; g_cnt2[1] = 1;   // slot 1 read at top of round 0
        g_maxMisKey = 0; g_M = 0; g_P = 0;
    }
}

// Persistent kernel: full MIS loop + clustering (R1-proven, frozen).
__global__ void __launch_bounds__(256, 4)
k_persist(const int* __restrict__ erow, const int* __restrict__ ecol,
          int n, int e, const float* __restrict__ x, int d,
          float* __restrict__ out)
{
    const unsigned nb = gridDim.x;
    const unsigned nt = nb * blockDim.x;
    const unsigned tid = blockIdx.x * blockDim.x + threadIdx.x;
    unsigned bt = 0;
    const bool vecok = ((e & 3) == 0);
    const unsigned e4 = (unsigned)e >> 2;

    for (int round = 0; round < 100000; ++round) {
        if (*((volatile int*)&g_cnt2[(round + 1) & 1]) == 0) break;

        // A: min-key propagation
        if (vecok) {
            for (unsigned i = tid; i < e4; i += nt) {
                int4 r = __ldg((const int4*)erow + i);
                int4 c = __ldg((const int4*)ecol + i);
                propF(r.x, c.x); propF(r.y, c.y);
                propF(r.z, c.z); propF(r.w, c.w);
            }
        } else {
            for (unsigned i = tid; i < (unsigned)e; i += nt)
                propF(erow[i], ecol[i]);
        }
        grid_bar(nb, bt);

        // B: local minima join MIS
        if (tid == 0) g_cnt2[(round + 1) & 1] = 0;
        for (unsigned v = tid; v < (unsigned)n; v += nt) {
            unsigned char m = g_mask[v];
            if (!m && g_key[v] == g_minNew[v]) { g_mis[v] = 1; g_mask[v] = 1; m = 1; }
            g_maskP[v] = m;
        }
        grid_bar(nb, bt);

        // C: mask dilation by exactly 1 hop
        if (vecok) {
            for (unsigned i = tid; i < e4; i += nt) {
                int4 r = __ldg((const int4*)erow + i);
                int4 c = __ldg((const int4*)ecol + i);
                dil(r.x, c.x); dil(r.y, c.y); dil(r.z, c.z); dil(r.w, c.w);
            }
        } else {
            for (unsigned i = tid; i < (unsigned)e; i += nt)
                dil(erow[i], ecol[i]);
        }
        grid_bar(nb, bt);

        // D: commit mask, reset min arrays, count unmasked
        int local = 0;
        for (unsigned v = tid; v < (unsigned)n; v += nt) {
            unsigned char m = g_maskP[v];
            g_mask[v] = m;
            unsigned long long val = m ? KINF : g_key[v];
            g_minCur[v] = val; g_minNew[v] = val;
            local += (m == 0);
        }
        int bs = block_reduce_add(local);
        if (threadIdx.x == 0 && bs) atomicAdd(&g_cnt2[round & 1], bs);
        grid_bar(nb, bt);
    }

    // ---------------- clustering ---------------------------------------------
    for (unsigned v = tid; v < (unsigned)n; v += nt) {
        unsigned long long mc;
        if (g_mis[v]) { mc = g_key[v]; atomicMax(&g_maxMisKey, mc); }
        else mc = KINF;
        g_minCur[v] = mc; g_minNew[v] = mc;
    }
    int chunk = (n + (int)nb - 1) / (int)nb;
    int cs = (int)blockIdx.x * chunk;
    int ce = cs + chunk; if (ce > n) ce = n;
    {
        int cnt = 0;
        for (int v = cs + (int)threadIdx.x; v < ce; v += (int)blockDim.x)
            cnt += g_mis[v];
        int bs = block_reduce_add(cnt);
        if (threadIdx.x == 0) g_nodeCnt[blockIdx.x] = bs;
    }
    grid_bar(nb, bt);

    if (blockIdx.x == 0 && threadIdx.x == 0) {
        int s = 0;
        for (unsigned i = 0; i < nb; ++i) { int c = g_nodeCnt[i]; g_nodeOff[i] = s; s += c; }
        if (s > MMAX) s = MMAX;
        g_M = s;
    }
    grid_bar(nb, bt);

    {
        int run = g_nodeOff[blockIdx.x];
        for (int t0 = cs; t0 < ce; t0 += (int)blockDim.x) {
            int v = t0 + (int)threadIdx.x;
            int f = (v < ce) ? (int)g_mis[v] : 0;
            int tot;
            int ex = block_excl_scan(f, tot);
            if (v < ce) g_misIdx[v] = run + ex;
            run += tot;
        }
    }
    grid_bar(nb, bt);

    // H: one min-key propagation (k = 1), full edge list
    if (vecok) {
        for (unsigned i = tid; i < e4; i += nt) {
            int4 r = __ldg((const int4*)erow + i);
            int4 c = __ldg((const int4*)ecol + i);
            propF(r.x, c.x); propF(r.y, c.y); propF(r.z, c.z); propF(r.w, c.w);
        }
    } else {
        for (unsigned i = tid; i < (unsigned)e; i += nt)
            propF(erow[i], ecol[i]);
    }
    grid_bar(nb, bt);

    // I: cluster assignment
    int fb = g_misIdx[(unsigned)(g_maxMisKey & 0xffffffffULL)];
    for (unsigned v = tid; v < (unsigned)n; v += nt) {
        unsigned long long mk = g_minNew[v];
        g_cluster[v] = (mk == KINF) ? fb : g_misIdx[(unsigned)(mk & 0xffffffffULL)];
    }

    // J: x_out = x[mis]
    if ((d & 3) == 0) {
        int dv = d >> 2;
        for (unsigned v = tid; v < (unsigned)n; v += nt) {
            if (g_mis[v]) {
                const float4* src = (const float4*)(x + (size_t)v * d);
                float4* dst = (float4*)(out + (size_t)g_misIdx[v] * d);
                for (int j = 0; j < dv; ++j) dst[j] = src[j];
            }
        }
    } else {
        for (unsigned v = tid; v < (unsigned)n; v += nt) {
            if (g_mis[v]) {
                const float* src = x + (size_t)v * d;
                float* dst = out + (size_t)g_misIdx[v] * d;
                for (int j = 0; j < d; ++j) dst[j] = src[j];
            }
        }
    }
}

// ---------------- dense pipeline (u32 fixed-point, R15-proven) -----------------
// inc = round(attr*2^16) + 1: +1 guarantees presence (acc != 0).
// atomicAdd return value UNUSED -> RED (fast path).
// Chunk decomposition shared by k_count and k_write (multiple of 4 cells).

__global__ void k_zero() {
    size_t MM = (size_t)g_M * (size_t)g_M;
    size_t nt = (size_t)gridDim.x * blockDim.x;
    for (size_t i = (size_t)blockIdx.x * blockDim.x + threadIdx.x; i < MM; i += nt)
        g_dense[i] = 0u;
}

__global__ void k_accum(const int* __restrict__ erow, const int* __restrict__ ecol,
                        const float* __restrict__ attr, int e) {
    unsigned M = (unsigned)g_M;
    unsigned nt = gridDim.x * blockDim.x;
    unsigned t = blockIdx.x * blockDim.x + threadIdx.x;
    const float SC = 65536.0f;
    if ((e & 3) == 0) {
        unsigned e4 = (unsigned)e >> 2;
        for (unsigned i = t; i < e4; i += nt) {
            int4 r = __ldg((const int4*)erow + i);
            int4 c = __ldg((const int4*)ecol + i);
            float4 a = __ldg((const float4*)attr + i);
            unsigned i0 = (unsigned)g_cluster[r.x] * M + (unsigned)g_cluster[c.x];
            unsigned i1 = (unsigned)g_cluster[r.y] * M + (unsigned)g_cluster[c.y];
            unsigned i2 = (unsigned)g_cluster[r.z] * M + (unsigned)g_cluster[c.z];
            unsigned i3 = (unsigned)g_cluster[r.w] * M + (unsigned)g_cluster[c.w];
            atomicAdd(&g_dense[i0], __float2uint_rn(a.x * SC) + 1u);
            atomicAdd(&g_dense[i1], __float2uint_rn(a.y * SC) + 1u);
            atomicAdd(&g_dense[i2], __float2uint_rn(a.z * SC) + 1u);
            atomicAdd(&g_dense[i3], __float2uint_rn(a.w * SC) + 1u);
        }
    } else {
        for (unsigned i = t; i < (unsigned)e; i += nt) {
            unsigned idx = (unsigned)g_cluster[erow[i]] * M + (unsigned)g_cluster[ecol[i]];
            atomicAdd(&g_dense[idx], __float2uint_rn(attr[i] * SC) + 1u);
        }
    }
}

// k_count: uint4-vectorized presence count (chunk = multiple of 4, matches k_write).
__global__ void k_count() {
    unsigned M = (unsigned)g_M;
    size_t MM = (size_t)M * M;
    size_t chunk = (((MM + gridDim.x - 1) / gridDim.x) + 3) & ~(size_t)3;
    size_t s = (size_t)blockIdx.x * chunk;
    int cnt = 0;
    if (s < MM) {
        size_t epos = s + chunk; if (epos > MM) epos = MM;
        size_t n4 = (epos - s) >> 2;
        const uint4* p4 = (const uint4*)(g_dense + s);
        for (size_t j = threadIdx.x; j < n4; j += blockDim.x) {
            uint4 v = p4[j];
            unsigned i0 = (unsigned)(s + (j << 2));
            if (v.x) { unsigned r = i0 / M;       cnt += (i0       - r * M) != r; }
            if (v.y) { unsigned r = (i0+1) / M;   cnt += ((i0+1)   - r * M) != r; }
            if (v.z) { unsigned r = (i0+2) / M;   cnt += ((i0+2)   - r * M) != r; }
            if (v.w) { unsigned r = (i0+3) / M;   cnt += ((i0+3)   - r * M) != r; }
        }
        for (size_t i = s + (n4 << 2) + threadIdx.x; i < epos; i += blockDim.x) {
            if (g_dense[i]) {
                unsigned ii = (unsigned)i;
                unsigned r = ii / M;
                cnt += ((ii - r * M) != r);
            }
        }
    }
    int bs = block_reduce_add(cnt);
    if (threadIdx.x == 0) g_cellCnt[blockIdx.x] = bs;
}

__global__ void k_scan(int nb2) {
    int t = threadIdx.x;
    int v = (t < nb2) ? g_cellCnt[t] : 0;
    int tot;
    int ex = block_excl_scan(v, tot);
    if (t < nb2) g_cellOff[t] = ex;
    if (t == 0) g_P = tot;
}

// k_write: ballot-based tile compaction (order preserved).
__global__ void k_write(float* __restrict__ out, int d) {
    __shared__ int wtot[8];
    unsigned M = (unsigned)g_M;
    size_t MM = (size_t)M * M;
    size_t P = (size_t)g_P;
    size_t xoff = (size_t)M * (size_t)d;
    size_t chunk = (((MM + gridDim.x - 1) / gridDim.x) + 3) & ~(size_t)3;
    size_t s = (size_t)blockIdx.x * chunk;
    if (s >= MM) return;
    size_t epos = s + chunk; if (epos > MM) epos = MM;
    size_t base = (size_t)g_cellOff[blockIdx.x];
    const float INV = 1.0f / 65536.0f;
    int lane = threadIdx.x & 31;
    int wid = threadIdx.x >> 5;
    unsigned lmask = (1u << lane) - 1u;

    for (size_t t0 = s; t0 < epos; t0 += blockDim.x) {
        size_t i = t0 + threadIdx.x;
        int keep = 0; unsigned r = 0, c = 0; float val = 0.f;
        if (i < epos) {
            unsigned a = g_dense[i];
            if (a != 0u) {
                unsigned ii = (unsigned)i;
                r = ii / M; c = ii - r * M;
                if (r != c) { keep = 1; val = (float)a * INV; }
            }
        }
        unsigned bal = __ballot_sync(0xffffffffu, keep);
        if (lane == 0) wtot[wid] = __popc(bal);
        __syncthreads();
        int pre = 0, tileTot = 0;
        #pragma unroll
        for (int w2 = 0; w2 < 8; ++w2) {
            int v2 = wtot[w2];
            pre += (w2 < wid) ? v2 : 0;
            tileTot += v2;
        }
        if (keep) {
            size_t p = base + (size_t)(pre + __popc(bal & lmask));
            out[xoff + p] = (float)r;
            out[xoff + P + p] = (float)c;
            out[xoff + 2 * P + p] = val;
        }
        base += (size_t)tileTot;
        __syncthreads();
    }
}

__global__ void k_tail(float* __restrict__ out, const float* __restrict__ score,
                       int n, int d) {
    int v = blockIdx.x * blockDim.x + threadIdx.x;
    if (v >= n) return;
    size_t off = (size_t)g_M * (size_t)d + 3 * (size_t)g_P;
    out[off + v] = (float)g_cluster[v];
    out[off + (size_t)n + v] = g_mis[v] ? 1.0f : 0.0f;
    out[off + 2 * (size_t)n + v] = score[v];
}

// ---------------- entry -------------------------------------------------------
extern "C" void kernel_launch(void* const* d_in, const int* in_sizes, int n_in,
                              void* d_out, int out_size) {
    const float* x = (const float*)d_in[0];
    const int* ei = (const int*)d_in[1];
    const float* attr = (const float*)d_in[2];
    const float* score = (const float*)d_in[3];
    int n = in_sizes[3];
    int e = in_sizes[1] / 2;
    int d = in_sizes[0] / n;
    const int* erow = ei;
    const int* ecol = ei + e;
    float* out = (float*)d_out;

    int dev = 0;
    cudaGetDevice(&dev);
    int sms = 148;
    cudaDeviceGetAttribute(&sms, cudaDevAttrMultiProcessorCount, dev);
    int nb = sms * 2;              // R17: halve blocks -> halve grid-barrier cost
    if (nb > MAXB) nb = MAXB;

    k_init<<<(n + 255) / 256, 256>>>(score, n);
    k_persist<<<nb, 256>>>(erow, ecol, n, e, x, d, out);
    k_zero<<<2048, 256>>>();
    k_accum<<<4096, 256>>>(erow, ecol, attr, e);
    k_count<<<MAXB, 256>>>();
    k_scan<<<1, 1024>>>(MAXB);
    k_write<<<MAXB, 256>>>(out, d);
    k_tail<<<(n + 255) / 256, 256>>>(out, score, n, d);
}